// round 1
// baseline (speedup 1.0000x reference)
#include <cuda_runtime.h>
#include <math.h>

#define Bn   8
#define Ln   9216
#define Cn   512
#define Hn   8
#define DK   64
#define HID  2048
#define Mrows (Bn*Ln)          // 73728

// ---------------- scratch (device globals: no runtime allocation) ----------
__device__ float g_xn [Mrows*Cn];
__device__ float g_vn [Mrows*Cn];
__device__ float g_q  [Mrows*Cn];
__device__ float g_k  [Mrows*Cn];
__device__ float g_val[Mrows*Cn];
__device__ float g_ctx[Bn*Hn*DK*DK];
__device__ float g_agg [Mrows*Cn];   // (B, Cv, L) channel-major
__device__ float g_attn[Mrows*Cn];   // reproj + xn^T, flat == (M, C) reinterpret
__device__ float g_x1 [Mrows*Cn];
__device__ float g_x1n[Mrows*Cn];
__device__ float g_h1 [Mrows*HID];

// ---------------- helpers ---------------------------------------------------
__device__ __forceinline__ float gelu_exact(float x) {
    return 0.5f * x * (1.0f + erff(x * 0.70710678118654752f));
}

__device__ __forceinline__ float blockReduceSum256(float v, float* s8, int tid) {
    #pragma unroll
    for (int o = 16; o > 0; o >>= 1) v += __shfl_xor_sync(0xffffffffu, v, o);
    int lane = tid & 31, w = tid >> 5;
    if (lane == 0) s8[w] = v;
    __syncthreads();
    if (w == 0) {
        v = (lane < 8) ? s8[lane] : 0.f;
        #pragma unroll
        for (int o = 4; o > 0; o >>= 1) v += __shfl_xor_sync(0xffffffffu, v, o);
        if (lane == 0) s8[0] = v;
    }
    __syncthreads();
    float r = s8[0];
    __syncthreads();
    return r;
}

// ---------------- LayerNorm: one block per row (C=512, 256 thr x 2) ---------
__global__ void ln_kernel(const float* __restrict__ in, const float* __restrict__ w,
                          const float* __restrict__ b, float* __restrict__ out) {
    __shared__ float s8[8];
    int row = blockIdx.x, t = threadIdx.x;
    size_t base = (size_t)row * Cn;
    float v0 = in[base + t], v1 = in[base + t + 256];
    float mean = blockReduceSum256(v0 + v1, s8, t) * (1.0f / Cn);
    float d0 = v0 - mean, d1 = v1 - mean;
    float var = blockReduceSum256(d0*d0 + d1*d1, s8, t) * (1.0f / Cn);
    float rs = rsqrtf(var + 1e-5f);
    out[base + t]       = d0 * rs * w[t]       + b[t];
    out[base + t + 256] = d1 * rs * w[t + 256] + b[t + 256];
}

// x1 = attn_flat + x ; x1n = LN(x1)
__global__ void x1_ln_kernel(const float* __restrict__ attn, const float* __restrict__ x,
                             const float* __restrict__ w, const float* __restrict__ b,
                             float* __restrict__ x1, float* __restrict__ x1n) {
    __shared__ float s8[8];
    int row = blockIdx.x, t = threadIdx.x;
    size_t base = (size_t)row * Cn;
    float v0 = attn[base + t]       + x[base + t];
    float v1 = attn[base + t + 256] + x[base + t + 256];
    x1[base + t] = v0; x1[base + t + 256] = v1;
    float mean = blockReduceSum256(v0 + v1, s8, t) * (1.0f / Cn);
    float d0 = v0 - mean, d1 = v1 - mean;
    float var = blockReduceSum256(d0*d0 + d1*d1, s8, t) * (1.0f / Cn);
    float rs = rsqrtf(var + 1e-5f);
    x1n[base + t]       = d0 * rs * w[t]       + b[t];
    x1n[base + t + 256] = d1 * rs * w[t + 256] + b[t + 256];
}

// ---------------- GEMM (NT): C[M,N] = A[M,K] * W[N,K]^T + bias --------------
// EPI: 0 = bias only, 1 = bias+gelu, 2 = bias+residual
template<int EPI>
__global__ __launch_bounds__(256)
void gemm_nt(const float* __restrict__ A, const float* __restrict__ W,
             const float* __restrict__ bias, const float* __restrict__ res,
             float* __restrict__ C, int Msz, int Nsz, int Ksz) {
    __shared__ float sA[16][128];
    __shared__ float sB[16][128];
    int tid = threadIdx.x;
    int m0 = blockIdx.y * 128, n0 = blockIdx.x * 128;
    int lr = tid >> 2;               // 0..63
    int lc = (tid & 3) << 2;         // 0,4,8,12
    int tx = tid & 15, ty = tid >> 4;

    float acc[8][8];
    #pragma unroll
    for (int i = 0; i < 8; i++)
        #pragma unroll
        for (int j = 0; j < 8; j++) acc[i][j] = 0.f;

    const float* Ap = A + (size_t)(m0 + lr) * Ksz + lc;
    const float* Wp = W + (size_t)(n0 + lr) * Ksz + lc;
    size_t half = (size_t)64 * Ksz;

    for (int kt = 0; kt < Ksz; kt += 16) {
        float4 a0 = *(const float4*)(Ap + kt);
        float4 a1 = *(const float4*)(Ap + kt + half);
        float4 b0 = *(const float4*)(Wp + kt);
        float4 b1 = *(const float4*)(Wp + kt + half);
        sA[lc+0][lr] = a0.x; sA[lc+1][lr] = a0.y; sA[lc+2][lr] = a0.z; sA[lc+3][lr] = a0.w;
        sA[lc+0][lr+64] = a1.x; sA[lc+1][lr+64] = a1.y; sA[lc+2][lr+64] = a1.z; sA[lc+3][lr+64] = a1.w;
        sB[lc+0][lr] = b0.x; sB[lc+1][lr] = b0.y; sB[lc+2][lr] = b0.z; sB[lc+3][lr] = b0.w;
        sB[lc+0][lr+64] = b1.x; sB[lc+1][lr+64] = b1.y; sB[lc+2][lr+64] = b1.z; sB[lc+3][lr+64] = b1.w;
        __syncthreads();
        #pragma unroll
        for (int k = 0; k < 16; k++) {
            float4 xa0 = *(const float4*)&sA[k][ty*8];
            float4 xa1 = *(const float4*)&sA[k][ty*8+4];
            float4 yb0 = *(const float4*)&sB[k][tx*8];
            float4 yb1 = *(const float4*)&sB[k][tx*8+4];
            float av[8] = {xa0.x,xa0.y,xa0.z,xa0.w,xa1.x,xa1.y,xa1.z,xa1.w};
            float bv[8] = {yb0.x,yb0.y,yb0.z,yb0.w,yb1.x,yb1.y,yb1.z,yb1.w};
            #pragma unroll
            for (int i = 0; i < 8; i++)
                #pragma unroll
                for (int j = 0; j < 8; j++) acc[i][j] = fmaf(av[i], bv[j], acc[i][j]);
        }
        __syncthreads();
    }

    #pragma unroll
    for (int i = 0; i < 8; i++) {
        int m = m0 + ty*8 + i;
        size_t rowb = (size_t)m * Nsz + n0 + tx*8;
        #pragma unroll
        for (int j = 0; j < 8; j++) {
            float v = acc[i][j] + bias[n0 + tx*8 + j];
            if (EPI == 1) v = gelu_exact(v);
            if (EPI == 2) v += res[rowb + j];
            C[rowb + j] = v;
        }
    }
}

// ---------------- reproj (NN): attn[z, m, n] = wr[m,:] . agg[z,:,n] + br + xn^T
__global__ __launch_bounds__(256)
void gemm_reproj(const float* __restrict__ Wr, const float* __restrict__ br,
                 const float* __restrict__ agg, const float* __restrict__ xn,
                 float* __restrict__ attn) {
    __shared__ float sA[16][128];
    __shared__ float sB[16][128];
    int z = blockIdx.z;
    int tid = threadIdx.x;
    int m0 = blockIdx.y * 128, n0 = blockIdx.x * 128;
    int lr = tid >> 2, lc = (tid & 3) << 2;
    int kr = tid >> 5;               // 0..7
    int nc = (tid & 31) << 2;        // 0..124
    int tx = tid & 15, ty = tid >> 4;

    float acc[8][8];
    #pragma unroll
    for (int i = 0; i < 8; i++)
        #pragma unroll
        for (int j = 0; j < 8; j++) acc[i][j] = 0.f;

    const float* Bb = agg + (size_t)z * Cn * Ln;

    for (int kt = 0; kt < Cn; kt += 16) {
        float4 a0 = *(const float4*)&Wr[(size_t)(m0 + lr) * Cn + kt + lc];
        float4 a1 = *(const float4*)&Wr[(size_t)(m0 + lr + 64) * Cn + kt + lc];
        sA[lc+0][lr] = a0.x; sA[lc+1][lr] = a0.y; sA[lc+2][lr] = a0.z; sA[lc+3][lr] = a0.w;
        sA[lc+0][lr+64] = a1.x; sA[lc+1][lr+64] = a1.y; sA[lc+2][lr+64] = a1.z; sA[lc+3][lr+64] = a1.w;
        float4 b0 = *(const float4*)&Bb[(size_t)(kt + kr) * Ln + n0 + nc];
        float4 b1 = *(const float4*)&Bb[(size_t)(kt + kr + 8) * Ln + n0 + nc];
        *(float4*)&sB[kr][nc]     = b0;
        *(float4*)&sB[kr + 8][nc] = b1;
        __syncthreads();
        #pragma unroll
        for (int k = 0; k < 16; k++) {
            float4 xa0 = *(const float4*)&sA[k][ty*8];
            float4 xa1 = *(const float4*)&sA[k][ty*8+4];
            float4 yb0 = *(const float4*)&sB[k][tx*8];
            float4 yb1 = *(const float4*)&sB[k][tx*8+4];
            float av[8] = {xa0.x,xa0.y,xa0.z,xa0.w,xa1.x,xa1.y,xa1.z,xa1.w};
            float bv[8] = {yb0.x,yb0.y,yb0.z,yb0.w,yb1.x,yb1.y,yb1.z,yb1.w};
            #pragma unroll
            for (int i = 0; i < 8; i++)
                #pragma unroll
                for (int j = 0; j < 8; j++) acc[i][j] = fmaf(av[i], bv[j], acc[i][j]);
        }
        __syncthreads();
    }

    #pragma unroll
    for (int i = 0; i < 8; i++) {
        int m = m0 + ty*8 + i;
        float bm = br[m];
        #pragma unroll
        for (int j = 0; j < 8; j++) {
            int n = n0 + tx*8 + j;
            float v = acc[i][j] + bm + xn[((size_t)(z*Ln + n)) * Cn + m];
            attn[(size_t)z * Cn * Ln + (size_t)m * Ln + n] = v;
        }
    }
}

// ---------------- k softmax over L (per (b, ck)) ----------------------------
// block (8,32): tx = channel-in-group, ty = l-lane
__global__ void k_softmax(float* __restrict__ k) {
    __shared__ float red[32][8];
    int tx = threadIdx.x, ty = threadIdx.y;
    int ck = blockIdx.x * 8 + tx;
    int b  = blockIdx.y;
    size_t base = (size_t)b * Ln * Cn + ck;

    float m = -1e30f;
    for (int l = ty; l < Ln; l += 32) m = fmaxf(m, k[base + (size_t)l * Cn]);
    red[ty][tx] = m; __syncthreads();
    #pragma unroll
    for (int st = 16; st > 0; st >>= 1) {
        if (ty < st) red[ty][tx] = fmaxf(red[ty][tx], red[ty + st][tx]);
        __syncthreads();
    }
    m = red[0][tx]; __syncthreads();

    float s = 0.f;
    for (int l = ty; l < Ln; l += 32) s += __expf(k[base + (size_t)l * Cn] - m);
    red[ty][tx] = s; __syncthreads();
    #pragma unroll
    for (int st = 16; st > 0; st >>= 1) {
        if (ty < st) red[ty][tx] += red[ty + st][tx];
        __syncthreads();
    }
    s = red[0][tx]; __syncthreads();
    float inv = 1.0f / s;

    for (int l = ty; l < Ln; l += 32) {
        size_t idx = base + (size_t)l * Cn;
        k[idx] = __expf(k[idx] - m) * inv;
    }
}

// ---------------- q softmax over dk=64 (one warp per (row, head)) -----------
__global__ void q_softmax(float* __restrict__ q) {
    int row = blockIdx.x;
    int w = threadIdx.x >> 5, lane = threadIdx.x & 31;
    size_t base = (size_t)row * Cn + w * DK;
    float a = q[base + lane], b = q[base + 32 + lane];
    float m = fmaxf(a, b);
    #pragma unroll
    for (int o = 16; o > 0; o >>= 1) m = fmaxf(m, __shfl_xor_sync(0xffffffffu, m, o));
    float e1 = __expf(a - m), e2 = __expf(b - m);
    float s = e1 + e2;
    #pragma unroll
    for (int o = 16; o > 0; o >>= 1) s += __shfl_xor_sync(0xffffffffu, s, o);
    float inv = 1.0f / s;
    q[base + lane]      = e1 * inv;
    q[base + 32 + lane] = e2 * inv;
}

// ---------------- zero ctx ---------------------------------------------------
__global__ void zero_kernel(float* __restrict__ p, int n) {
    int i = blockIdx.x * blockDim.x + threadIdx.x;
    if (i < n) p[i] = 0.f;
}

// ---------------- context[b,h,k,v] += sum_l ksm * val (split-L atomics) -----
__global__ __launch_bounds__(256)
void context_kernel(const float* __restrict__ ksm, const float* __restrict__ val,
                    float* __restrict__ ctx) {
    __shared__ float sK[8][64];
    __shared__ float sV[8][64];
    int b = blockIdx.z, h = blockIdx.y;
    int l0 = blockIdx.x * (Ln / 16);
    int tid = threadIdx.x;
    int tx = tid & 15, ty = tid >> 4;
    int li = tid >> 5, cc = tid & 31;

    float acc[4][4] = {};
    for (int lc = l0; lc < l0 + Ln / 16; lc += 8) {
        size_t idx = ((size_t)(b * Ln + lc + li)) * Cn + h * DK + cc;
        sK[li][cc]      = ksm[idx];
        sK[li][cc + 32] = ksm[idx + 32];
        sV[li][cc]      = val[idx];
        sV[li][cc + 32] = val[idx + 32];
        __syncthreads();
        #pragma unroll
        for (int l = 0; l < 8; l++) {
            float kv[4], vv[4];
            #pragma unroll
            for (int i = 0; i < 4; i++) { kv[i] = sK[l][ty*4+i]; vv[i] = sV[l][tx*4+i]; }
            #pragma unroll
            for (int i = 0; i < 4; i++)
                #pragma unroll
                for (int j = 0; j < 4; j++) acc[i][j] = fmaf(kv[i], vv[j], acc[i][j]);
        }
        __syncthreads();
    }
    size_t cb = (size_t)(b * Hn + h) * DK * DK;
    #pragma unroll
    for (int i = 0; i < 4; i++)
        #pragma unroll
        for (int j = 0; j < 4; j++)
            atomicAdd(&ctx[cb + (size_t)(ty*4+i) * DK + tx*4+j], acc[i][j]);
}

// ---------------- agg[b, h*64+v, l] = sum_k ctx[b,h,k,v] * qsm[b,l,h,k] ------
__global__ __launch_bounds__(256)
void agg_kernel(const float* __restrict__ qsm, const float* __restrict__ ctx,
                float* __restrict__ agg) {
    __shared__ float sC[64][64];    // [k][v]
    __shared__ float sQ[128][64];   // [l][k]
    int b = blockIdx.z, h = blockIdx.y, l0 = blockIdx.x * 128;
    int tid = threadIdx.x;
    int tx = tid & 15, ty = tid >> 4;

    size_t cb = (size_t)(b * Hn + h) * DK * DK;
    for (int f = tid; f < 4096; f += 256) sC[f >> 6][f & 63] = ctx[cb + f];
    for (int f = tid; f < 8192; f += 256) {
        int l = f >> 6, kk = f & 63;
        sQ[l][kk] = qsm[((size_t)(b * Ln + l0 + l)) * Cn + h * DK + kk];
    }
    __syncthreads();

    // thread: v = tx*4+i (4), l = ty*8+j (8)
    float acc[4][8] = {};
    #pragma unroll
    for (int k = 0; k < 64; k++) {
        float cv[4], qv[8];
        #pragma unroll
        for (int i = 0; i < 4; i++) cv[i] = sC[k][tx*4+i];
        #pragma unroll
        for (int j = 0; j < 8; j++) qv[j] = sQ[ty*8+j][k];
        #pragma unroll
        for (int i = 0; i < 4; i++)
            #pragma unroll
            for (int j = 0; j < 8; j++) acc[i][j] = fmaf(cv[i], qv[j], acc[i][j]);
    }
    #pragma unroll
    for (int i = 0; i < 4; i++) {
        size_t ob = ((size_t)((b * Hn + h) * DK + tx*4+i)) * Ln + l0 + ty*8;
        float4 w0 = make_float4(acc[i][0], acc[i][1], acc[i][2], acc[i][3]);
        float4 w1 = make_float4(acc[i][4], acc[i][5], acc[i][6], acc[i][7]);
        *(float4*)&agg[ob]     = w0;
        *(float4*)&agg[ob + 4] = w1;
    }
}

// ---------------- host launcher ---------------------------------------------
extern "C" void kernel_launch(void* const* d_in, const int* in_sizes, int n_in,
                              void* d_out, int out_size) {
    (void)in_sizes; (void)n_in; (void)out_size;
    const float* x     = (const float*)d_in[0];
    const float* v     = (const float*)d_in[1];
    const float* ln1_w = (const float*)d_in[4];
    const float* ln1_b = (const float*)d_in[5];
    const float* lnv_w = (const float*)d_in[6];
    const float* lnv_b = (const float*)d_in[7];
    const float* ln2_w = (const float*)d_in[8];
    const float* ln2_b = (const float*)d_in[9];
    const float* wq    = (const float*)d_in[10];
    const float* bq    = (const float*)d_in[11];
    const float* wk    = (const float*)d_in[12];
    const float* bk    = (const float*)d_in[13];
    const float* wv    = (const float*)d_in[14];
    const float* bv    = (const float*)d_in[15];
    const float* wr    = (const float*)d_in[16];
    const float* br    = (const float*)d_in[17];
    const float* fc1_w = (const float*)d_in[18];
    const float* fc1_b = (const float*)d_in[19];
    const float* fc2_w = (const float*)d_in[20];
    const float* fc2_b = (const float*)d_in[21];
    float* out = (float*)d_out;

    float *p_xn, *p_vn, *p_q, *p_k, *p_val, *p_ctx, *p_agg, *p_attn, *p_x1, *p_x1n, *p_h1;
    cudaGetSymbolAddress((void**)&p_xn,  g_xn);
    cudaGetSymbolAddress((void**)&p_vn,  g_vn);
    cudaGetSymbolAddress((void**)&p_q,   g_q);
    cudaGetSymbolAddress((void**)&p_k,   g_k);
    cudaGetSymbolAddress((void**)&p_val, g_val);
    cudaGetSymbolAddress((void**)&p_ctx, g_ctx);
    cudaGetSymbolAddress((void**)&p_agg, g_agg);
    cudaGetSymbolAddress((void**)&p_attn,g_attn);
    cudaGetSymbolAddress((void**)&p_x1,  g_x1);
    cudaGetSymbolAddress((void**)&p_x1n, g_x1n);
    cudaGetSymbolAddress((void**)&p_h1,  g_h1);

    // 1) LayerNorms
    ln_kernel<<<Mrows, 256>>>(x, ln1_w, ln1_b, p_xn);
    ln_kernel<<<Mrows, 256>>>(v, lnv_w, lnv_b, p_vn);

    // 2) q/k/val projections (NT GEMMs)
    dim3 gqkv(Cn / 128, Mrows / 128);
    gemm_nt<0><<<gqkv, 256>>>(p_xn, wq, bq, nullptr, p_q,   Mrows, Cn, Cn);
    gemm_nt<0><<<gqkv, 256>>>(p_vn, wk, bk, nullptr, p_k,   Mrows, Cn, Cn);
    gemm_nt<0><<<gqkv, 256>>>(p_vn, wv, bv, nullptr, p_val, Mrows, Cn, Cn);

    // 3) softmaxes
    k_softmax<<<dim3(Cn / 8, Bn), dim3(8, 32)>>>(p_k);
    q_softmax<<<Mrows, 256>>>(p_q);

    // 4) context = k_sm^T @ val  (split-L + atomics)
    zero_kernel<<<(Bn*Hn*DK*DK + 255) / 256, 256>>>(p_ctx, Bn*Hn*DK*DK);
    context_kernel<<<dim3(16, Hn, Bn), 256>>>(p_k, p_val, p_ctx);

    // 5) agg = ctx^T @ q_sm  -> (B, Cv, L)
    agg_kernel<<<dim3(Ln / 128, Hn, Bn), 256>>>(p_q, p_ctx, p_agg);

    // 6) reproj + xn^T residual -> flat attn buffer
    gemm_reproj<<<dim3(Ln / 128, Cn / 128, Bn), 256>>>(wr, br, p_agg, p_xn, p_attn);

    // 7) x1 = attn + x ; x1n = LN(x1)
    x1_ln_kernel<<<Mrows, 256>>>(p_attn, x, ln2_w, ln2_b, p_x1, p_x1n);

    // 8) MLP
    gemm_nt<1><<<dim3(HID / 128, Mrows / 128), 256>>>(p_x1n, fc1_w, fc1_b, nullptr, p_h1, Mrows, HID, Cn);
    gemm_nt<2><<<dim3(Cn / 128, Mrows / 128), 256>>>(p_h1, fc2_w, fc2_b, p_x1, out, Mrows, Cn, HID);
}

// round 2
// speedup vs baseline: 1.6769x; 1.6769x over previous
#include <cuda_runtime.h>
#include <math.h>

#define Bn   8
#define Ln   9216
#define Cn   512
#define Hn   8
#define DK   64
#define HID  2048
#define Mrows (Bn*Ln)          // 73728
#define TS   20                // smem row stride in words (KT=16 + pad 4)

// ---------------- scratch (device globals: no runtime allocation) ----------
__device__ float g_xn [Mrows*Cn];
__device__ float g_vn [Mrows*Cn];
__device__ float g_q  [Mrows*Cn];
__device__ float g_k  [Mrows*Cn];
__device__ float g_val[Mrows*Cn];
__device__ float g_ctx[Bn*Hn*DK*DK];
__device__ float g_agg [Mrows*Cn];   // (B, Cv, L) channel-major
__device__ float g_attn[Mrows*Cn];   // reproj + xn^T, flat == (M, C) reinterpret
__device__ float g_x1 [Mrows*Cn];
__device__ float g_x1n[Mrows*Cn];
__device__ float g_h1 [Mrows*HID];

// ---------------- helpers ---------------------------------------------------
__device__ __forceinline__ float gelu_exact(float x) {
    return 0.5f * x * (1.0f + erff(x * 0.70710678118654752f));
}

__device__ __forceinline__ unsigned f2tf32(float x) {
    unsigned r;
    asm("cvt.rna.tf32.f32 %0, %1;" : "=r"(r) : "f"(x));
    return r;
}

__device__ __forceinline__ void mma_tf32(float* c, const unsigned* a, const unsigned* b) {
    asm volatile(
        "mma.sync.aligned.m16n8k8.row.col.f32.tf32.tf32.f32 "
        "{%0,%1,%2,%3}, {%4,%5,%6,%7}, {%8,%9}, {%0,%1,%2,%3};"
        : "+f"(c[0]), "+f"(c[1]), "+f"(c[2]), "+f"(c[3])
        : "r"(a[0]), "r"(a[1]), "r"(a[2]), "r"(a[3]), "r"(b[0]), "r"(b[1]));
}

__device__ __forceinline__ float blockReduceSum256(float v, float* s8, int tid) {
    #pragma unroll
    for (int o = 16; o > 0; o >>= 1) v += __shfl_xor_sync(0xffffffffu, v, o);
    int lane = tid & 31, w = tid >> 5;
    if (lane == 0) s8[w] = v;
    __syncthreads();
    if (w == 0) {
        v = (lane < 8) ? s8[lane] : 0.f;
        #pragma unroll
        for (int o = 4; o > 0; o >>= 1) v += __shfl_xor_sync(0xffffffffu, v, o);
        if (lane == 0) s8[0] = v;
    }
    __syncthreads();
    float r = s8[0];
    __syncthreads();
    return r;
}

// ---------------- LayerNorm -------------------------------------------------
__global__ void ln_kernel(const float* __restrict__ in, const float* __restrict__ w,
                          const float* __restrict__ b, float* __restrict__ out) {
    __shared__ float s8[8];
    int row = blockIdx.x, t = threadIdx.x;
    size_t base = (size_t)row * Cn;
    float v0 = in[base + t], v1 = in[base + t + 256];
    float mean = blockReduceSum256(v0 + v1, s8, t) * (1.0f / Cn);
    float d0 = v0 - mean, d1 = v1 - mean;
    float var = blockReduceSum256(d0*d0 + d1*d1, s8, t) * (1.0f / Cn);
    float rs = rsqrtf(var + 1e-5f);
    out[base + t]       = d0 * rs * w[t]       + b[t];
    out[base + t + 256] = d1 * rs * w[t + 256] + b[t + 256];
}

__global__ void x1_ln_kernel(const float* __restrict__ attn, const float* __restrict__ x,
                             const float* __restrict__ w, const float* __restrict__ b,
                             float* __restrict__ x1, float* __restrict__ x1n) {
    __shared__ float s8[8];
    int row = blockIdx.x, t = threadIdx.x;
    size_t base = (size_t)row * Cn;
    float v0 = attn[base + t]       + x[base + t];
    float v1 = attn[base + t + 256] + x[base + t + 256];
    x1[base + t] = v0; x1[base + t + 256] = v1;
    float mean = blockReduceSum256(v0 + v1, s8, t) * (1.0f / Cn);
    float d0 = v0 - mean, d1 = v1 - mean;
    float var = blockReduceSum256(d0*d0 + d1*d1, s8, t) * (1.0f / Cn);
    float rs = rsqrtf(var + 1e-5f);
    x1n[base + t]       = d0 * rs * w[t]       + b[t];
    x1n[base + t + 256] = d1 * rs * w[t + 256] + b[t + 256];
}

// ---------------- tf32 GEMM (NT): C[M,N] = A[M,K] * W[N,K]^T + bias ---------
// 128x128 CTA tile, KT=16, 8 warps each 64x32 via m16n8k8.
// EPI: 0 = bias, 1 = bias+gelu, 2 = bias+residual
template<int EPI>
__global__ __launch_bounds__(256)
void gemm_tf32(const float* __restrict__ A, const float* __restrict__ W,
               const float* __restrict__ bias, const float* __restrict__ res,
               float* __restrict__ C, int Msz, int Nsz, int Ksz) {
    __shared__ unsigned sA[2][128*TS];
    __shared__ unsigned sB[2][128*TS];
    int tid = threadIdx.x;
    int m0 = blockIdx.y * 128, n0 = blockIdx.x * 128;
    int warp = tid >> 5, lane = tid & 31;
    int wm = (warp & 1) * 64, wn = (warp >> 1) * 32;
    int q = lane >> 2, r = lane & 3;

    int lrow = tid >> 2;          // 0..63
    int lcol = (tid & 3) * 4;     // 0,4,8,12

    const float* Ap = A + (size_t)(m0 + lrow) * Ksz + lcol;
    const float* Wp = W + (size_t)(n0 + lrow) * Ksz + lcol;
    size_t half = (size_t)64 * Ksz;

    float acc[4][4][4];
    #pragma unroll
    for (int i = 0; i < 4; i++)
        #pragma unroll
        for (int j = 0; j < 4; j++)
            #pragma unroll
            for (int c = 0; c < 4; c++) acc[i][j][c] = 0.f;

    float4 ra[2], rb[2];
    ra[0] = *(const float4*)(Ap);        ra[1] = *(const float4*)(Ap + half);
    rb[0] = *(const float4*)(Wp);        rb[1] = *(const float4*)(Wp + half);
    #pragma unroll
    for (int i = 0; i < 2; i++) {
        unsigned* pa = &sA[0][(lrow + i*64) * TS + lcol];
        pa[0]=f2tf32(ra[i].x); pa[1]=f2tf32(ra[i].y); pa[2]=f2tf32(ra[i].z); pa[3]=f2tf32(ra[i].w);
        unsigned* pb = &sB[0][(lrow + i*64) * TS + lcol];
        pb[0]=f2tf32(rb[i].x); pb[1]=f2tf32(rb[i].y); pb[2]=f2tf32(rb[i].z); pb[3]=f2tf32(rb[i].w);
    }
    __syncthreads();

    int nk = Ksz >> 4;
    for (int kt = 0; kt < nk; kt++) {
        int buf = kt & 1;
        if (kt + 1 < nk) {
            const float* Ap2 = Ap + (kt + 1) * 16;
            const float* Wp2 = Wp + (kt + 1) * 16;
            ra[0] = *(const float4*)(Ap2);        ra[1] = *(const float4*)(Ap2 + half);
            rb[0] = *(const float4*)(Wp2);        rb[1] = *(const float4*)(Wp2 + half);
        }
        #pragma unroll
        for (int ks = 0; ks < 2; ks++) {
            unsigned af[4][4], bf[4][2];
            #pragma unroll
            for (int mt = 0; mt < 4; mt++) {
                const unsigned* base = &sA[buf][(wm + mt*16 + q) * TS + ks*8 + r];
                af[mt][0] = base[0];
                af[mt][1] = base[8*TS];
                af[mt][2] = base[4];
                af[mt][3] = base[8*TS + 4];
            }
            #pragma unroll
            for (int nt = 0; nt < 4; nt++) {
                const unsigned* base = &sB[buf][(wn + nt*8 + q) * TS + ks*8 + r];
                bf[nt][0] = base[0];
                bf[nt][1] = base[4];
            }
            #pragma unroll
            for (int mt = 0; mt < 4; mt++)
                #pragma unroll
                for (int nt = 0; nt < 4; nt++)
                    mma_tf32(acc[mt][nt], af[mt], bf[nt]);
        }
        if (kt + 1 < nk) {
            #pragma unroll
            for (int i = 0; i < 2; i++) {
                unsigned* pa = &sA[buf^1][(lrow + i*64) * TS + lcol];
                pa[0]=f2tf32(ra[i].x); pa[1]=f2tf32(ra[i].y); pa[2]=f2tf32(ra[i].z); pa[3]=f2tf32(ra[i].w);
                unsigned* pb = &sB[buf^1][(lrow + i*64) * TS + lcol];
                pb[0]=f2tf32(rb[i].x); pb[1]=f2tf32(rb[i].y); pb[2]=f2tf32(rb[i].z); pb[3]=f2tf32(rb[i].w);
            }
        }
        __syncthreads();
    }

    #pragma unroll
    for (int mt = 0; mt < 4; mt++) {
        int m = m0 + wm + mt*16 + q;
        #pragma unroll
        for (int nt = 0; nt < 4; nt++) {
            int n = n0 + wn + nt*8 + r*2;
            float b0 = bias[n], b1 = bias[n+1];
            float v0 = acc[mt][nt][0] + b0, v1 = acc[mt][nt][1] + b1;
            float v2 = acc[mt][nt][2] + b0, v3 = acc[mt][nt][3] + b1;
            if (EPI == 1) { v0 = gelu_exact(v0); v1 = gelu_exact(v1); v2 = gelu_exact(v2); v3 = gelu_exact(v3); }
            size_t o0 = (size_t)m * Nsz + n;
            size_t o1 = (size_t)(m + 8) * Nsz + n;
            if (EPI == 2) { v0 += res[o0]; v1 += res[o0+1]; v2 += res[o1]; v3 += res[o1+1]; }
            float2 w0 = make_float2(v0, v1);
            float2 w1 = make_float2(v2, v3);
            *(float2*)&C[o0] = w0;
            *(float2*)&C[o1] = w1;
        }
    }
}

// ---------------- reproj tf32 (NN): attn[z,m,n] = wr[m,:].agg[z,:,n]+br+xn^T
__global__ __launch_bounds__(256)
void gemm_reproj_tf32(const float* __restrict__ Wr, const float* __restrict__ br,
                      const float* __restrict__ agg, const float* __restrict__ xn,
                      float* __restrict__ attn) {
    __shared__ unsigned sA[2][128*TS];
    __shared__ unsigned sB[2][128*TS];
    int z = blockIdx.z;
    int tid = threadIdx.x;
    int m0 = blockIdx.y * 128, n0 = blockIdx.x * 128;
    int warp = tid >> 5, lane = tid & 31;
    int wm = (warp & 1) * 64, wn = (warp >> 1) * 32;
    int q = lane >> 2, r = lane & 3;

    // A load mapping (Wr [512,512] row-major, like NT)
    int lrowA = tid >> 2;          // 0..63
    int lcolA = (tid & 3) * 4;
    const float* Ap = Wr + (size_t)(m0 + lrowA) * Cn + lcolA;
    size_t halfA = (size_t)64 * Cn;
    // B load mapping (agg [C rows, L cols]; tile 16 k-rows x 128 n-cols)
    int krow = tid >> 4;           // 0..15
    int nc4  = (tid & 15) * 4;     // 0..60
    const float* Bb = agg + (size_t)z * Cn * Ln + (size_t)krow * Ln + n0 + nc4;

    float acc[4][4][4];
    #pragma unroll
    for (int i = 0; i < 4; i++)
        #pragma unroll
        for (int j = 0; j < 4; j++)
            #pragma unroll
            for (int c = 0; c < 4; c++) acc[i][j][c] = 0.f;

    float4 ra[2], rb[2];
    ra[0] = *(const float4*)(Ap);         ra[1] = *(const float4*)(Ap + halfA);
    rb[0] = *(const float4*)(Bb);         rb[1] = *(const float4*)(Bb + 64);
    #pragma unroll
    for (int i = 0; i < 2; i++) {
        unsigned* pa = &sA[0][(lrowA + i*64) * TS + lcolA];
        pa[0]=f2tf32(ra[i].x); pa[1]=f2tf32(ra[i].y); pa[2]=f2tf32(ra[i].z); pa[3]=f2tf32(ra[i].w);
        int nb = nc4 + i*64;
        sB[0][(nb+0)*TS + krow] = f2tf32(rb[i].x);
        sB[0][(nb+1)*TS + krow] = f2tf32(rb[i].y);
        sB[0][(nb+2)*TS + krow] = f2tf32(rb[i].z);
        sB[0][(nb+3)*TS + krow] = f2tf32(rb[i].w);
    }
    __syncthreads();

    int nk = Cn >> 4;   // 32
    for (int kt = 0; kt < nk; kt++) {
        int buf = kt & 1;
        if (kt + 1 < nk) {
            const float* Ap2 = Ap + (kt + 1) * 16;
            const float* Bb2 = Bb + (size_t)(kt + 1) * 16 * Ln;
            ra[0] = *(const float4*)(Ap2);         ra[1] = *(const float4*)(Ap2 + halfA);
            rb[0] = *(const float4*)(Bb2);         rb[1] = *(const float4*)(Bb2 + 64);
        }
        #pragma unroll
        for (int ks = 0; ks < 2; ks++) {
            unsigned af[4][4], bf[4][2];
            #pragma unroll
            for (int mt = 0; mt < 4; mt++) {
                const unsigned* base = &sA[buf][(wm + mt*16 + q) * TS + ks*8 + r];
                af[mt][0] = base[0];
                af[mt][1] = base[8*TS];
                af[mt][2] = base[4];
                af[mt][3] = base[8*TS + 4];
            }
            #pragma unroll
            for (int nt = 0; nt < 4; nt++) {
                const unsigned* base = &sB[buf][(wn + nt*8 + q) * TS + ks*8 + r];
                bf[nt][0] = base[0];
                bf[nt][1] = base[4];
            }
            #pragma unroll
            for (int mt = 0; mt < 4; mt++)
                #pragma unroll
                for (int nt = 0; nt < 4; nt++)
                    mma_tf32(acc[mt][nt], af[mt], bf[nt]);
        }
        if (kt + 1 < nk) {
            #pragma unroll
            for (int i = 0; i < 2; i++) {
                unsigned* pa = &sA[buf^1][(lrowA + i*64) * TS + lcolA];
                pa[0]=f2tf32(ra[i].x); pa[1]=f2tf32(ra[i].y); pa[2]=f2tf32(ra[i].z); pa[3]=f2tf32(ra[i].w);
                int nb = nc4 + i*64;
                sB[buf^1][(nb+0)*TS + krow] = f2tf32(rb[i].x);
                sB[buf^1][(nb+1)*TS + krow] = f2tf32(rb[i].y);
                sB[buf^1][(nb+2)*TS + krow] = f2tf32(rb[i].z);
                sB[buf^1][(nb+3)*TS + krow] = f2tf32(rb[i].w);
            }
        }
        __syncthreads();
    }

    #pragma unroll
    for (int mt = 0; mt < 4; mt++) {
        int m = m0 + wm + mt*16 + q;
        float bm0 = br[m], bm1 = br[m + 8];
        #pragma unroll
        for (int nt = 0; nt < 4; nt++) {
            int n = n0 + wn + nt*8 + r*2;
            float v0 = acc[mt][nt][0] + bm0 + xn[((size_t)(z*Ln + n    )) * Cn + m];
            float v1 = acc[mt][nt][1] + bm0 + xn[((size_t)(z*Ln + n + 1)) * Cn + m];
            float v2 = acc[mt][nt][2] + bm1 + xn[((size_t)(z*Ln + n    )) * Cn + m + 8];
            float v3 = acc[mt][nt][3] + bm1 + xn[((size_t)(z*Ln + n + 1)) * Cn + m + 8];
            size_t ob = (size_t)z * Cn * Ln + (size_t)m * Ln + n;
            float2 w0 = make_float2(v0, v1);
            float2 w1 = make_float2(v2, v3);
            *(float2*)&attn[ob]          = w0;
            *(float2*)&attn[ob + 8*Ln]   = w1;
        }
    }
}

// ---------------- k softmax over L (per (b, ck)) ----------------------------
__global__ void k_softmax(float* __restrict__ k) {
    __shared__ float red[32][8];
    int tx = threadIdx.x, ty = threadIdx.y;
    int ck = blockIdx.x * 8 + tx;
    int b  = blockIdx.y;
    size_t base = (size_t)b * Ln * Cn + ck;

    float m = -1e30f;
    for (int l = ty; l < Ln; l += 32) m = fmaxf(m, k[base + (size_t)l * Cn]);
    red[ty][tx] = m; __syncthreads();
    #pragma unroll
    for (int st = 16; st > 0; st >>= 1) {
        if (ty < st) red[ty][tx] = fmaxf(red[ty][tx], red[ty + st][tx]);
        __syncthreads();
    }
    m = red[0][tx]; __syncthreads();

    float s = 0.f;
    for (int l = ty; l < Ln; l += 32) s += __expf(k[base + (size_t)l * Cn] - m);
    red[ty][tx] = s; __syncthreads();
    #pragma unroll
    for (int st = 16; st > 0; st >>= 1) {
        if (ty < st) red[ty][tx] += red[ty + st][tx];
        __syncthreads();
    }
    s = red[0][tx]; __syncthreads();
    float inv = 1.0f / s;

    for (int l = ty; l < Ln; l += 32) {
        size_t idx = base + (size_t)l * Cn;
        k[idx] = __expf(k[idx] - m) * inv;
    }
}

// ---------------- q softmax over dk=64 --------------------------------------
__global__ void q_softmax(float* __restrict__ q) {
    int row = blockIdx.x;
    int w = threadIdx.x >> 5, lane = threadIdx.x & 31;
    size_t base = (size_t)row * Cn + w * DK;
    float a = q[base + lane], b = q[base + 32 + lane];
    float m = fmaxf(a, b);
    #pragma unroll
    for (int o = 16; o > 0; o >>= 1) m = fmaxf(m, __shfl_xor_sync(0xffffffffu, m, o));
    float e1 = __expf(a - m), e2 = __expf(b - m);
    float s = e1 + e2;
    #pragma unroll
    for (int o = 16; o > 0; o >>= 1) s += __shfl_xor_sync(0xffffffffu, s, o);
    float inv = 1.0f / s;
    q[base + lane]      = e1 * inv;
    q[base + 32 + lane] = e2 * inv;
}

__global__ void zero_kernel(float* __restrict__ p, int n) {
    int i = blockIdx.x * blockDim.x + threadIdx.x;
    if (i < n) p[i] = 0.f;
}

// ---------------- context[b,h,k,v] += sum_l ksm * val -----------------------
__global__ __launch_bounds__(256)
void context_kernel(const float* __restrict__ ksm, const float* __restrict__ val,
                    float* __restrict__ ctx) {
    __shared__ float sK[8][64];
    __shared__ float sV[8][64];
    int b = blockIdx.z, h = blockIdx.y;
    int l0 = blockIdx.x * (Ln / 16);
    int tid = threadIdx.x;
    int tx = tid & 15, ty = tid >> 4;
    int li = tid >> 5, cc = tid & 31;

    float acc[4][4] = {};
    for (int lc = l0; lc < l0 + Ln / 16; lc += 8) {
        size_t idx = ((size_t)(b * Ln + lc + li)) * Cn + h * DK + cc;
        sK[li][cc]      = ksm[idx];
        sK[li][cc + 32] = ksm[idx + 32];
        sV[li][cc]      = val[idx];
        sV[li][cc + 32] = val[idx + 32];
        __syncthreads();
        #pragma unroll
        for (int l = 0; l < 8; l++) {
            float kv[4], vv[4];
            #pragma unroll
            for (int i = 0; i < 4; i++) { kv[i] = sK[l][ty*4+i]; vv[i] = sV[l][tx*4+i]; }
            #pragma unroll
            for (int i = 0; i < 4; i++)
                #pragma unroll
                for (int j = 0; j < 4; j++) acc[i][j] = fmaf(kv[i], vv[j], acc[i][j]);
        }
        __syncthreads();
    }
    size_t cb = (size_t)(b * Hn + h) * DK * DK;
    #pragma unroll
    for (int i = 0; i < 4; i++)
        #pragma unroll
        for (int j = 0; j < 4; j++)
            atomicAdd(&ctx[cb + (size_t)(ty*4+i) * DK + tx*4+j], acc[i][j]);
}

// ---------------- agg[b, h*64+v, l] = sum_k ctx[b,h,k,v] * qsm[b,l,h,k] ------
__global__ __launch_bounds__(256)
void agg_kernel(const float* __restrict__ qsm, const float* __restrict__ ctx,
                float* __restrict__ agg) {
    __shared__ float sC[64][64];
    __shared__ float sQ[128][64];
    int b = blockIdx.z, h = blockIdx.y, l0 = blockIdx.x * 128;
    int tid = threadIdx.x;
    int tx = tid & 15, ty = tid >> 4;

    size_t cb = (size_t)(b * Hn + h) * DK * DK;
    for (int f = tid; f < 4096; f += 256) sC[f >> 6][f & 63] = ctx[cb + f];
    for (int f = tid; f < 8192; f += 256) {
        int l = f >> 6, kk = f & 63;
        sQ[l][kk] = qsm[((size_t)(b * Ln + l0 + l)) * Cn + h * DK + kk];
    }
    __syncthreads();

    float acc[4][8] = {};
    #pragma unroll
    for (int k = 0; k < 64; k++) {
        float cv[4], qv[8];
        #pragma unroll
        for (int i = 0; i < 4; i++) cv[i] = sC[k][tx*4+i];
        #pragma unroll
        for (int j = 0; j < 8; j++) qv[j] = sQ[ty*8+j][k];
        #pragma unroll
        for (int i = 0; i < 4; i++)
            #pragma unroll
            for (int j = 0; j < 8; j++) acc[i][j] = fmaf(cv[i], qv[j], acc[i][j]);
    }
    #pragma unroll
    for (int i = 0; i < 4; i++) {
        size_t ob = ((size_t)((b * Hn + h) * DK + tx*4+i)) * Ln + l0 + ty*8;
        float4 w0 = make_float4(acc[i][0], acc[i][1], acc[i][2], acc[i][3]);
        float4 w1 = make_float4(acc[i][4], acc[i][5], acc[i][6], acc[i][7]);
        *(float4*)&agg[ob]     = w0;
        *(float4*)&agg[ob + 4] = w1;
    }
}

// ---------------- host launcher ---------------------------------------------
extern "C" void kernel_launch(void* const* d_in, const int* in_sizes, int n_in,
                              void* d_out, int out_size) {
    (void)in_sizes; (void)n_in; (void)out_size;
    const float* x     = (const float*)d_in[0];
    const float* v     = (const float*)d_in[1];
    const float* ln1_w = (const float*)d_in[4];
    const float* ln1_b = (const float*)d_in[5];
    const float* lnv_w = (const float*)d_in[6];
    const float* lnv_b = (const float*)d_in[7];
    const float* ln2_w = (const float*)d_in[8];
    const float* ln2_b = (const float*)d_in[9];
    const float* wq    = (const float*)d_in[10];
    const float* bq    = (const float*)d_in[11];
    const float* wk    = (const float*)d_in[12];
    const float* bk    = (const float*)d_in[13];
    const float* wv    = (const float*)d_in[14];
    const float* bv    = (const float*)d_in[15];
    const float* wr    = (const float*)d_in[16];
    const float* br    = (const float*)d_in[17];
    const float* fc1_w = (const float*)d_in[18];
    const float* fc1_b = (const float*)d_in[19];
    const float* fc2_w = (const float*)d_in[20];
    const float* fc2_b = (const float*)d_in[21];
    float* out = (float*)d_out;

    float *p_xn, *p_vn, *p_q, *p_k, *p_val, *p_ctx, *p_agg, *p_attn, *p_x1, *p_x1n, *p_h1;
    cudaGetSymbolAddress((void**)&p_xn,  g_xn);
    cudaGetSymbolAddress((void**)&p_vn,  g_vn);
    cudaGetSymbolAddress((void**)&p_q,   g_q);
    cudaGetSymbolAddress((void**)&p_k,   g_k);
    cudaGetSymbolAddress((void**)&p_val, g_val);
    cudaGetSymbolAddress((void**)&p_ctx, g_ctx);
    cudaGetSymbolAddress((void**)&p_agg, g_agg);
    cudaGetSymbolAddress((void**)&p_attn,g_attn);
    cudaGetSymbolAddress((void**)&p_x1,  g_x1);
    cudaGetSymbolAddress((void**)&p_x1n, g_x1n);
    cudaGetSymbolAddress((void**)&p_h1,  g_h1);

    // 1) LayerNorms
    ln_kernel<<<Mrows, 256>>>(x, ln1_w, ln1_b, p_xn);
    ln_kernel<<<Mrows, 256>>>(v, lnv_w, lnv_b, p_vn);

    // 2) q/k/val projections (tf32 tensor-core GEMMs)
    dim3 gqkv(Cn / 128, Mrows / 128);
    gemm_tf32<0><<<gqkv, 256>>>(p_xn, wq, bq, nullptr, p_q,   Mrows, Cn, Cn);
    gemm_tf32<0><<<gqkv, 256>>>(p_vn, wk, bk, nullptr, p_k,   Mrows, Cn, Cn);
    gemm_tf32<0><<<gqkv, 256>>>(p_vn, wv, bv, nullptr, p_val, Mrows, Cn, Cn);

    // 3) softmaxes
    k_softmax<<<dim3(Cn / 8, Bn), dim3(8, 32)>>>(p_k);
    q_softmax<<<Mrows, 256>>>(p_q);

    // 4) context = k_sm^T @ val
    zero_kernel<<<(Bn*Hn*DK*DK + 255) / 256, 256>>>(p_ctx, Bn*Hn*DK*DK);
    context_kernel<<<dim3(16, Hn, Bn), 256>>>(p_k, p_val, p_ctx);

    // 5) agg = ctx^T @ q_sm  -> (B, Cv, L)
    agg_kernel<<<dim3(Ln / 128, Hn, Bn), 256>>>(p_q, p_ctx, p_agg);

    // 6) reproj + xn^T residual -> flat attn buffer
    gemm_reproj_tf32<<<dim3(Ln / 128, Cn / 128, Bn), 256>>>(wr, br, p_agg, p_xn, p_attn);

    // 7) x1 = attn + x ; x1n = LN(x1)
    x1_ln_kernel<<<Mrows, 256>>>(p_attn, x, ln2_w, ln2_b, p_x1, p_x1n);

    // 8) MLP
    gemm_tf32<1><<<dim3(HID / 128, Mrows / 128), 256>>>(p_x1n, fc1_w, fc1_b, nullptr, p_h1, Mrows, HID, Cn);
    gemm_tf32<2><<<dim3(Cn / 128, Mrows / 128), 256>>>(p_h1, fc2_w, fc2_b, p_x1, out, Mrows, Cn, HID);
}

// round 4
// speedup vs baseline: 4.3342x; 2.5846x over previous
#include <cuda_runtime.h>
#include <cuda_bf16.h>
#include <math.h>
#include <stdint.h>

#define Bn   8
#define Ln   9216
#define Cn   512
#define Hn   8
#define DK   64
#define HID  2048
#define Mrows (Bn*Ln)          // 73728

// ---------------- scratch (device globals: no runtime allocation) ----------
__device__ float          g_xn  [Mrows*Cn];   // fp32 xn (reproj epilogue addend)
__device__ __nv_bfloat16  g_xnb [Mrows*Cn];   // bf16 xn (GEMM A)
__device__ __nv_bfloat16  g_vnb [Mrows*Cn];   // bf16 vn (GEMM A)
__device__ float          g_q   [Mrows*Cn];
__device__ float          g_k   [Mrows*Cn];
__device__ float          g_val [Mrows*Cn];
__device__ float          g_ctx [Bn*Hn*DK*DK];
__device__ __nv_bfloat16  g_aggT[Mrows*Cn];   // (B, L, C) bf16 (reproj B operand)
__device__ float          g_attn[Mrows*Cn];   // reproj + xn, flat == (M, C) reinterpret
__device__ float          g_x1  [Mrows*Cn];
__device__ __nv_bfloat16  g_x1nb[Mrows*Cn];   // bf16 LN2 out (fc1 A)
__device__ __nv_bfloat16  g_h1b [Mrows*HID];  // bf16 gelu(fc1) (fc2 A)
// bf16 weights
__device__ __nv_bfloat16  g_wqb [Cn*Cn];
__device__ __nv_bfloat16  g_wkb [Cn*Cn];
__device__ __nv_bfloat16  g_wvb [Cn*Cn];
__device__ __nv_bfloat16  g_wrb [Cn*Cn];
__device__ __nv_bfloat16  g_f1b [HID*Cn];
__device__ __nv_bfloat16  g_f2b [Cn*HID];

// ---------------- asm helpers ------------------------------------------------
__device__ __forceinline__ uint32_t smem_u32(const void* p) {
    uint32_t a;
    asm("{ .reg .u64 t; cvta.to.shared.u64 t, %1; cvt.u32.u64 %0, t; }" : "=r"(a) : "l"(p));
    return a;
}
__device__ __forceinline__ void ldsm4(uint32_t* r, uint32_t a) {
    asm volatile("ldmatrix.sync.aligned.m8n8.x4.shared.b16 {%0,%1,%2,%3}, [%4];"
        : "=r"(r[0]), "=r"(r[1]), "=r"(r[2]), "=r"(r[3]) : "r"(a));
}
__device__ __forceinline__ void mma_bf16(float* c, const uint32_t* a, const uint32_t* b) {
    asm volatile("mma.sync.aligned.m16n8k16.row.col.f32.bf16.bf16.f32 "
        "{%0,%1,%2,%3}, {%4,%5,%6,%7}, {%8,%9}, {%0,%1,%2,%3};"
        : "+f"(c[0]), "+f"(c[1]), "+f"(c[2]), "+f"(c[3])
        : "r"(a[0]), "r"(a[1]), "r"(a[2]), "r"(a[3]), "r"(b[0]), "r"(b[1]));
}
__device__ __forceinline__ void cp16(uint32_t dst, const void* src) {
    asm volatile("cp.async.cg.shared.global [%0], [%1], 16;" :: "r"(dst), "l"(src));
}
#define CP_COMMIT() asm volatile("cp.async.commit_group;" ::: "memory")
#define CP_WAIT3()  asm volatile("cp.async.wait_group 3;" ::: "memory")

// smem tile geometry: rows of 32 bf16 (64B) padded to 80B -> conflict-free LDSM
#define ROWB   80
#define STG_A  (128*ROWB)          // 10240
#define STG    (2*STG_A)           // 20480 per stage
#define NST    4
#define SMEM_REQ (NST*STG)         // 81920

// ---------------- misc device helpers ---------------------------------------
__device__ __forceinline__ float gelu_exact(float x) {
    return 0.5f * x * (1.0f + erff(x * 0.70710678118654752f));
}

__device__ __forceinline__ float blockReduceSum256(float v, float* s8, int tid) {
    #pragma unroll
    for (int o = 16; o > 0; o >>= 1) v += __shfl_xor_sync(0xffffffffu, v, o);
    int lane = tid & 31, w = tid >> 5;
    if (lane == 0) s8[w] = v;
    __syncthreads();
    if (w == 0) {
        v = (lane < 8) ? s8[lane] : 0.f;
        #pragma unroll
        for (int o = 4; o > 0; o >>= 1) v += __shfl_xor_sync(0xffffffffu, v, o);
        if (lane == 0) s8[0] = v;
    }
    __syncthreads();
    float r = s8[0];
    __syncthreads();
    return r;
}

// ---------------- bf16 GEMM (NT): C[M,N] = A[M,K]·W[N,K]^T + epilogue -------
// CTA 128x128, K-chunk 32, 4-stage cp.async, ldmatrix + mma m16n8k16.
// EPI: 0 bias(n) -> f32        1 bias(n)+gelu -> bf16
//      2 bias(n)+res -> f32    3 reproj: br(m) + xn gather, out stride Ln -> f32
template<int EPI>
__global__ __launch_bounds__(256)
void gemm_bf16(const __nv_bfloat16* __restrict__ A, const __nv_bfloat16* __restrict__ W,
               const float* __restrict__ bias, const float* __restrict__ res,
               void* __restrict__ Cout, int Msz, int Nsz, int Ksz) {
    extern __shared__ char smem[];
    uint32_t sbase = smem_u32(smem);

    int tid = threadIdx.x;
    int wid = tid >> 5, lane = tid & 31;
    int m0 = blockIdx.y * 128, n0 = blockIdx.x * 128;
    int wm = (wid & 1) * 64, wn = (wid >> 1) * 32;
    int lrow = lane & 15;
    int lko  = (lane >> 4) * 16;

    const __nv_bfloat16* Aop = A;
    const __nv_bfloat16* Wop = W;
    const float* resp = res;
    float* CpF = (float*)Cout;
    __nv_bfloat16* CpH = (__nv_bfloat16*)Cout;
    if (EPI == 3) {
        size_t z = blockIdx.z;
        Wop  = W + z * (size_t)Ln * Cn;     // aggT batch slice [L, C] bf16
        resp = res + z * (size_t)Ln * Cn;   // xn f32 batch slice [L, C]
        CpF  = (float*)Cout + z * (size_t)Cn * Ln;
    }

    float acc[4][4][4];
    #pragma unroll
    for (int i = 0; i < 4; i++)
        #pragma unroll
        for (int j = 0; j < 4; j++)
            #pragma unroll
            for (int c = 0; c < 4; c++) acc[i][j][c] = 0.f;

    int arow = tid >> 2;          // 0..63
    int acol = tid & 3;           // 0..3 (16B chunks of 8 bf16)

    auto load_chunk = [&](int kt, int s) {
        uint32_t dA = sbase + s * STG;
        uint32_t dB = dA + STG_A;
        const __nv_bfloat16* ga = Aop + (size_t)(m0 + arow) * Ksz + kt * 32 + acol * 8;
        cp16(dA + (uint32_t)(arow * ROWB + acol * 16), ga);
        cp16(dA + (uint32_t)((arow + 64) * ROWB + acol * 16), ga + (size_t)64 * Ksz);
        const __nv_bfloat16* gb = Wop + (size_t)(n0 + arow) * Ksz + kt * 32 + acol * 8;
        cp16(dB + (uint32_t)(arow * ROWB + acol * 16), gb);
        cp16(dB + (uint32_t)((arow + 64) * ROWB + acol * 16), gb + (size_t)64 * Ksz);
        CP_COMMIT();
    };

    int nk = Ksz >> 5;
    load_chunk(0, 0);
    load_chunk(1, 1);
    load_chunk(2, 2);
    load_chunk(3, 3);

    for (int kt = 0; kt < nk; kt++) {
        int s = kt & 3;
        CP_WAIT3();
        __syncthreads();
        uint32_t sA = sbase + s * STG;
        uint32_t sB = sA + STG_A;
        #pragma unroll
        for (int ks = 0; ks < 2; ks++) {
            uint32_t af[4][4], bf[2][4];
            #pragma unroll
            for (int mt = 0; mt < 4; mt++)
                ldsm4(af[mt], sA + (uint32_t)((wm + mt*16 + lrow) * ROWB + ks*32 + lko));
            #pragma unroll
            for (int g = 0; g < 2; g++)
                ldsm4(bf[g], sB + (uint32_t)((wn + g*16 + lrow) * ROWB + ks*32 + lko));
            #pragma unroll
            for (int mt = 0; mt < 4; mt++)
                #pragma unroll
                for (int nt = 0; nt < 4; nt++) {
                    uint32_t bb[2] = { bf[nt>>1][nt&1], bf[nt>>1][(nt&1) + 2] };
                    mma_bf16(acc[mt][nt], af[mt], bb);
                }
        }
        __syncthreads();
        if (kt + 4 < nk) load_chunk(kt + 4, s);
        else CP_COMMIT();           // keep group count uniform for wait_group
    }

    // -------- epilogue (direct STG from accumulators)
    int rm = lane >> 2, cn = (lane & 3) * 2;
    #pragma unroll
    for (int mt = 0; mt < 4; mt++) {
        int m = m0 + wm + mt*16 + rm;
        float bm0 = 0.f, bm1 = 0.f;
        if (EPI == 3) { bm0 = bias[m]; bm1 = bias[m + 8]; }
        #pragma unroll
        for (int nt = 0; nt < 4; nt++) {
            int n = n0 + wn + nt*8 + cn;
            float* c = acc[mt][nt];
            if (EPI == 0) {
                float2 bb = *(const float2*)&bias[n];
                *(float2*)&CpF[(size_t)m * Nsz + n]       = make_float2(c[0]+bb.x, c[1]+bb.y);
                *(float2*)&CpF[(size_t)(m+8) * Nsz + n]   = make_float2(c[2]+bb.x, c[3]+bb.y);
            } else if (EPI == 1) {
                float2 bb = *(const float2*)&bias[n];
                __nv_bfloat162 p0 = __floats2bfloat162_rn(gelu_exact(c[0]+bb.x), gelu_exact(c[1]+bb.y));
                __nv_bfloat162 p1 = __floats2bfloat162_rn(gelu_exact(c[2]+bb.x), gelu_exact(c[3]+bb.y));
                *(__nv_bfloat162*)&CpH[(size_t)m * Nsz + n]     = p0;
                *(__nv_bfloat162*)&CpH[(size_t)(m+8) * Nsz + n] = p1;
            } else if (EPI == 2) {
                float2 bb = *(const float2*)&bias[n];
                float2 r0 = *(const float2*)&resp[(size_t)m * Nsz + n];
                float2 r1 = *(const float2*)&resp[(size_t)(m+8) * Nsz + n];
                *(float2*)&CpF[(size_t)m * Nsz + n]     = make_float2(c[0]+bb.x+r0.x, c[1]+bb.y+r0.y);
                *(float2*)&CpF[(size_t)(m+8) * Nsz + n] = make_float2(c[2]+bb.x+r1.x, c[3]+bb.y+r1.y);
            } else {
                float x00 = resp[(size_t)n * Cn + m];
                float x01 = resp[(size_t)(n+1) * Cn + m];
                float x10 = resp[(size_t)n * Cn + m + 8];
                float x11 = resp[(size_t)(n+1) * Cn + m + 8];
                *(float2*)&CpF[(size_t)m * Ln + n]     = make_float2(c[0]+bm0+x00, c[1]+bm0+x01);
                *(float2*)&CpF[(size_t)(m+8) * Ln + n] = make_float2(c[2]+bm1+x10, c[3]+bm1+x11);
            }
        }
    }
}

// ---------------- f32 -> bf16 convert ----------------------------------------
__global__ void cvt_bf16_kernel(const float* __restrict__ in, __nv_bfloat16* __restrict__ out, int n) {
    int i = (blockIdx.x * blockDim.x + threadIdx.x) * 4;
    if (i < n) {
        float4 v = *(const float4*)(in + i);
        *(__nv_bfloat162*)(out + i)     = __floats2bfloat162_rn(v.x, v.y);
        *(__nv_bfloat162*)(out + i + 2) = __floats2bfloat162_rn(v.z, v.w);
    }
}

// ---------------- LayerNorm: bf16 out (+ optional f32 copy) ------------------
__global__ void ln_kernel(const float* __restrict__ in, const float* __restrict__ w,
                          const float* __restrict__ b, __nv_bfloat16* __restrict__ outb,
                          float* __restrict__ outf) {
    __shared__ float s8[8];
    int row = blockIdx.x, t = threadIdx.x;
    size_t base = (size_t)row * Cn;
    float v0 = in[base + t], v1 = in[base + t + 256];
    float mean = blockReduceSum256(v0 + v1, s8, t) * (1.0f / Cn);
    float d0 = v0 - mean, d1 = v1 - mean;
    float var = blockReduceSum256(d0*d0 + d1*d1, s8, t) * (1.0f / Cn);
    float rs = rsqrtf(var + 1e-5f);
    float o0 = d0 * rs * w[t]       + b[t];
    float o1 = d1 * rs * w[t + 256] + b[t + 256];
    outb[base + t]       = __float2bfloat16_rn(o0);
    outb[base + t + 256] = __float2bfloat16_rn(o1);
    if (outf) { outf[base + t] = o0; outf[base + t + 256] = o1; }
}

// x1 = attn_flat + x ; x1n = LN(x1) (bf16)
__global__ void x1_ln_kernel(const float* __restrict__ attn, const float* __restrict__ x,
                             const float* __restrict__ w, const float* __restrict__ b,
                             float* __restrict__ x1, __nv_bfloat16* __restrict__ x1nb) {
    __shared__ float s8[8];
    int row = blockIdx.x, t = threadIdx.x;
    size_t base = (size_t)row * Cn;
    float v0 = attn[base + t]       + x[base + t];
    float v1 = attn[base + t + 256] + x[base + t + 256];
    x1[base + t] = v0; x1[base + t + 256] = v1;
    float mean = blockReduceSum256(v0 + v1, s8, t) * (1.0f / Cn);
    float d0 = v0 - mean, d1 = v1 - mean;
    float var = blockReduceSum256(d0*d0 + d1*d1, s8, t) * (1.0f / Cn);
    float rs = rsqrtf(var + 1e-5f);
    x1nb[base + t]       = __float2bfloat16_rn(d0 * rs * w[t]       + b[t]);
    x1nb[base + t + 256] = __float2bfloat16_rn(d1 * rs * w[t + 256] + b[t + 256]);
}

// ---------------- k softmax over L (per (b, ck)) ----------------------------
__global__ void k_softmax(float* __restrict__ k) {
    __shared__ float red[32][8];
    int tx = threadIdx.x, ty = threadIdx.y;
    int ck = blockIdx.x * 8 + tx;
    int b  = blockIdx.y;
    size_t base = (size_t)b * Ln * Cn + ck;

    float m = -1e30f;
    for (int l = ty; l < Ln; l += 32) m = fmaxf(m, k[base + (size_t)l * Cn]);
    red[ty][tx] = m; __syncthreads();
    #pragma unroll
    for (int st = 16; st > 0; st >>= 1) {
        if (ty < st) red[ty][tx] = fmaxf(red[ty][tx], red[ty + st][tx]);
        __syncthreads();
    }
    m = red[0][tx]; __syncthreads();

    float s = 0.f;
    for (int l = ty; l < Ln; l += 32) s += __expf(k[base + (size_t)l * Cn] - m);
    red[ty][tx] = s; __syncthreads();
    #pragma unroll
    for (int st = 16; st > 0; st >>= 1) {
        if (ty < st) red[ty][tx] += red[ty + st][tx];
        __syncthreads();
    }
    s = red[0][tx]; __syncthreads();
    float inv = 1.0f / s;

    for (int l = ty; l < Ln; l += 32) {
        size_t idx = base + (size_t)l * Cn;
        k[idx] = __expf(k[idx] - m) * inv;
    }
}

// ---------------- q softmax over dk=64 --------------------------------------
__global__ void q_softmax(float* __restrict__ q) {
    int row = blockIdx.x;
    int w = threadIdx.x >> 5, lane = threadIdx.x & 31;
    size_t base = (size_t)row * Cn + w * DK;
    float a = q[base + lane], b = q[base + 32 + lane];
    float m = fmaxf(a, b);
    #pragma unroll
    for (int o = 16; o > 0; o >>= 1) m = fmaxf(m, __shfl_xor_sync(0xffffffffu, m, o));
    float e1 = __expf(a - m), e2 = __expf(b - m);
    float s = e1 + e2;
    #pragma unroll
    for (int o = 16; o > 0; o >>= 1) s += __shfl_xor_sync(0xffffffffu, s, o);
    float inv = 1.0f / s;
    q[base + lane]      = e1 * inv;
    q[base + 32 + lane] = e2 * inv;
}

__global__ void zero_kernel(float* __restrict__ p, int n) {
    int i = blockIdx.x * blockDim.x + threadIdx.x;
    if (i < n) p[i] = 0.f;
}

// ---------------- context[b,h,k,v] += sum_l ksm * val -----------------------
__global__ __launch_bounds__(256)
void context_kernel(const float* __restrict__ ksm, const float* __restrict__ val,
                    float* __restrict__ ctx) {
    __shared__ float sK[8][64];
    __shared__ float sV[8][64];
    int b = blockIdx.z, h = blockIdx.y;
    int l0 = blockIdx.x * (Ln / 16);
    int tid = threadIdx.x;
    int tx = tid & 15, ty = tid >> 4;
    int li = tid >> 5, cc = tid & 31;

    float acc[4][4] = {};
    for (int lc = l0; lc < l0 + Ln / 16; lc += 8) {
        size_t idx = ((size_t)(b * Ln + lc + li)) * Cn + h * DK + cc;
        sK[li][cc]      = ksm[idx];
        sK[li][cc + 32] = ksm[idx + 32];
        sV[li][cc]      = val[idx];
        sV[li][cc + 32] = val[idx + 32];
        __syncthreads();
        #pragma unroll
        for (int l = 0; l < 8; l++) {
            float kv[4], vv[4];
            #pragma unroll
            for (int i = 0; i < 4; i++) { kv[i] = sK[l][ty*4+i]; vv[i] = sV[l][tx*4+i]; }
            #pragma unroll
            for (int i = 0; i < 4; i++)
                #pragma unroll
                for (int j = 0; j < 4; j++) acc[i][j] = fmaf(kv[i], vv[j], acc[i][j]);
        }
        __syncthreads();
    }
    size_t cb = (size_t)(b * Hn + h) * DK * DK;
    #pragma unroll
    for (int i = 0; i < 4; i++)
        #pragma unroll
        for (int j = 0; j < 4; j++)
            atomicAdd(&ctx[cb + (size_t)(ty*4+i) * DK + tx*4+j], acc[i][j]);
}

// ---- aggT[b, l, h*64+v] = sum_k ctx[b,h,k,v] * qsm[b,l,h,k]  (bf16 out) ----
__global__ __launch_bounds__(256)
void agg_kernel(const float* __restrict__ qsm, const float* __restrict__ ctx,
                __nv_bfloat16* __restrict__ aggT) {
    __shared__ float sC[64][64];
    __shared__ float sQ[128][64];
    int b = blockIdx.z, h = blockIdx.y, l0 = blockIdx.x * 128;
    int tid = threadIdx.x;
    int tx = tid & 15, ty = tid >> 4;

    size_t cb = (size_t)(b * Hn + h) * DK * DK;
    for (int f = tid; f < 4096; f += 256) sC[f >> 6][f & 63] = ctx[cb + f];
    for (int f = tid; f < 8192; f += 256) {
        int l = f >> 6, kk = f & 63;
        sQ[l][kk] = qsm[((size_t)(b * Ln + l0 + l)) * Cn + h * DK + kk];
    }
    __syncthreads();

    float acc[4][8] = {};
    #pragma unroll
    for (int k = 0; k < 64; k++) {
        float cv[4], qv[8];
        #pragma unroll
        for (int i = 0; i < 4; i++) cv[i] = sC[k][tx*4+i];
        #pragma unroll
        for (int j = 0; j < 8; j++) qv[j] = sQ[ty*8+j][k];
        #pragma unroll
        for (int i = 0; i < 4; i++)
            #pragma unroll
            for (int j = 0; j < 8; j++) acc[i][j] = fmaf(cv[i], qv[j], acc[i][j]);
    }
    #pragma unroll
    for (int j = 0; j < 8; j++) {
        size_t ob = ((size_t)(b * Ln + l0 + ty*8 + j)) * Cn + h * DK + tx*4;
        *(__nv_bfloat162*)&aggT[ob]     = __floats2bfloat162_rn(acc[0][j], acc[1][j]);
        *(__nv_bfloat162*)&aggT[ob + 2] = __floats2bfloat162_rn(acc[2][j], acc[3][j]);
    }
}

// ---------------- host launcher ---------------------------------------------
extern "C" void kernel_launch(void* const* d_in, const int* in_sizes, int n_in,
                              void* d_out, int out_size) {
    (void)in_sizes; (void)n_in; (void)out_size;
    const float* x     = (const float*)d_in[0];
    const float* v     = (const float*)d_in[1];
    const float* ln1_w = (const float*)d_in[4];
    const float* ln1_b = (const float*)d_in[5];
    const float* lnv_w = (const float*)d_in[6];
    const float* lnv_b = (const float*)d_in[7];
    const float* ln2_w = (const float*)d_in[8];
    const float* ln2_b = (const float*)d_in[9];
    const float* wq    = (const float*)d_in[10];
    const float* bq    = (const float*)d_in[11];
    const float* wk    = (const float*)d_in[12];
    const float* bk    = (const float*)d_in[13];
    const float* wv    = (const float*)d_in[14];
    const float* bv    = (const float*)d_in[15];
    const float* wr    = (const float*)d_in[16];
    const float* br    = (const float*)d_in[17];
    const float* fc1_w = (const float*)d_in[18];
    const float* fc1_b = (const float*)d_in[19];
    const float* fc2_w = (const float*)d_in[20];
    const float* fc2_b = (const float*)d_in[21];
    float* out = (float*)d_out;

    float *p_xn, *p_q, *p_k, *p_val, *p_ctx, *p_attn, *p_x1;
    __nv_bfloat16 *p_xnb, *p_vnb, *p_aggT, *p_x1nb, *p_h1b;
    __nv_bfloat16 *p_wqb, *p_wkb, *p_wvb, *p_wrb, *p_f1b, *p_f2b;
    cudaGetSymbolAddress((void**)&p_xn,  g_xn);
    cudaGetSymbolAddress((void**)&p_xnb, g_xnb);
    cudaGetSymbolAddress((void**)&p_vnb, g_vnb);
    cudaGetSymbolAddress((void**)&p_q,   g_q);
    cudaGetSymbolAddress((void**)&p_k,   g_k);
    cudaGetSymbolAddress((void**)&p_val, g_val);
    cudaGetSymbolAddress((void**)&p_ctx, g_ctx);
    cudaGetSymbolAddress((void**)&p_aggT,g_aggT);
    cudaGetSymbolAddress((void**)&p_attn,g_attn);
    cudaGetSymbolAddress((void**)&p_x1,  g_x1);
    cudaGetSymbolAddress((void**)&p_x1nb,g_x1nb);
    cudaGetSymbolAddress((void**)&p_h1b, g_h1b);
    cudaGetSymbolAddress((void**)&p_wqb, g_wqb);
    cudaGetSymbolAddress((void**)&p_wkb, g_wkb);
    cudaGetSymbolAddress((void**)&p_wvb, g_wvb);
    cudaGetSymbolAddress((void**)&p_wrb, g_wrb);
    cudaGetSymbolAddress((void**)&p_f1b, g_f1b);
    cudaGetSymbolAddress((void**)&p_f2b, g_f2b);

    cudaFuncSetAttribute(gemm_bf16<0>, cudaFuncAttributeMaxDynamicSharedMemorySize, SMEM_REQ);
    cudaFuncSetAttribute(gemm_bf16<1>, cudaFuncAttributeMaxDynamicSharedMemorySize, SMEM_REQ);
    cudaFuncSetAttribute(gemm_bf16<2>, cudaFuncAttributeMaxDynamicSharedMemorySize, SMEM_REQ);
    cudaFuncSetAttribute(gemm_bf16<3>, cudaFuncAttributeMaxDynamicSharedMemorySize, SMEM_REQ);

    // 0) weight conversion (f32 -> bf16)
    cvt_bf16_kernel<<<(Cn*Cn/4 + 255)/256, 256>>>(wq, p_wqb, Cn*Cn);
    cvt_bf16_kernel<<<(Cn*Cn/4 + 255)/256, 256>>>(wk, p_wkb, Cn*Cn);
    cvt_bf16_kernel<<<(Cn*Cn/4 + 255)/256, 256>>>(wv, p_wvb, Cn*Cn);
    cvt_bf16_kernel<<<(Cn*Cn/4 + 255)/256, 256>>>(wr, p_wrb, Cn*Cn);
    cvt_bf16_kernel<<<(HID*Cn/4 + 255)/256, 256>>>(fc1_w, p_f1b, HID*Cn);
    cvt_bf16_kernel<<<(Cn*HID/4 + 255)/256, 256>>>(fc2_w, p_f2b, Cn*HID);

    // 1) LayerNorms
    ln_kernel<<<Mrows, 256>>>(x, ln1_w, ln1_b, p_xnb, p_xn);
    ln_kernel<<<Mrows, 256>>>(v, lnv_w, lnv_b, p_vnb, nullptr);

    // 2) q/k/val projections (bf16 mma)
    dim3 gqkv(Cn / 128, Mrows / 128);
    gemm_bf16<0><<<gqkv, 256, SMEM_REQ>>>(p_xnb, p_wqb, bq, nullptr, p_q,   Mrows, Cn, Cn);
    gemm_bf16<0><<<gqkv, 256, SMEM_REQ>>>(p_vnb, p_wkb, bk, nullptr, p_k,   Mrows, Cn, Cn);
    gemm_bf16<0><<<gqkv, 256, SMEM_REQ>>>(p_vnb, p_wvb, bv, nullptr, p_val, Mrows, Cn, Cn);

    // 3) softmaxes
    k_softmax<<<dim3(Cn / 8, Bn), dim3(8, 32)>>>(p_k);
    q_softmax<<<Mrows, 256>>>(p_q);

    // 4) context = k_sm^T @ val
    zero_kernel<<<(Bn*Hn*DK*DK + 255) / 256, 256>>>(p_ctx, Bn*Hn*DK*DK);
    context_kernel<<<dim3(16, Hn, Bn), 256>>>(p_k, p_val, p_ctx);

    // 5) aggT = (ctx^T @ q_sm)^T  -> (B, L, C) bf16
    agg_kernel<<<dim3(Ln / 128, Hn, Bn), 256>>>(p_q, p_ctx, p_aggT);

    // 6) reproj: attn[z,c,l] = wr[c,:]·aggT[z,l,:] + br[c] + xn[z,l,c]
    gemm_bf16<3><<<dim3(Ln / 128, Cn / 128, Bn), 256, SMEM_REQ>>>(
        p_wrb, p_aggT, br, p_xn, p_attn, Cn, Ln, Cn);

    // 7) x1 = attn + x ; x1n = LN(x1)
    x1_ln_kernel<<<Mrows, 256>>>(p_attn, x, ln2_w, ln2_b, p_x1, p_x1nb);

    // 8) MLP
    gemm_bf16<1><<<dim3(HID / 128, Mrows / 128), 256, SMEM_REQ>>>(
        p_x1nb, p_f1b, fc1_b, nullptr, p_h1b, Mrows, HID, Cn);
    gemm_bf16<2><<<dim3(Cn / 128, Mrows / 128), 256, SMEM_REQ>>>(
        p_h1b, p_f2b, fc2_b, p_x1, out, Mrows, Cn, HID);
}